// round 1
// baseline (speedup 1.0000x reference)
#include <cuda_runtime.h>
#include <math.h>

// Problem constants
#define BB 512
#define LL 25
#define EE 300
#define HH 1024
#define DD 256
#define TT 128
#define BL (BB*LL)          // 12800
#define CATW (DD+HH)        // 1280

// ---------------- scratch (device globals; no allocation allowed) -----------
__device__ float g_x[BL*EE];                    // renormed encoder embeddings
__device__ float g_gi_all[BL*3*HH];             // (B*L, 3H) input gates, all steps
__device__ float g_enc_out[BL*HH];              // (B*L, H) encoder outputs
__device__ float g_h[BB*HH];                    // recurrent hidden (enc then dec)
__device__ float g_gh[BB*3*HH];                 // h @ Whh^T
__device__ float g_cat[BB*CATW];                // [emb | applied]
__device__ float g_aw[BB*LL];                   // attention weights
__device__ float g_o[BB*HH];                    // combined+bn+relu
__device__ float g_gi_dec[BB*3*HH];             // decoder input gates
__device__ float g_hb[BB*HH];                   // bn1(h)
__device__ float g_logits[BB*TT];
__device__ int   g_inp[BB];

__device__ __forceinline__ float sigmoidf_(float x) { return 1.f/(1.f+expf(-x)); }

// ---------------- generic NT SGEMM: C(M,N) = A(M,K) * B(N,K)^T --------------
enum { EPI_NONE=0, EPI_BIAS=1, EPI_BN_RELU=2 };

template<int BM,int BN,int BK,int TM,int TN,int EPI>
__global__ void sgemm_nt(const float* __restrict__ A, const float* __restrict__ Bm,
                         float* __restrict__ C, int M, int N, int K,
                         const float* __restrict__ bias, const float* __restrict__ bn)
{
    __shared__ float As[BK][BM];
    __shared__ float Bs[BK][BN];
    const int tid  = threadIdx.x;
    const int NT   = (BM/TM)*(BN/TN);
    const int m0   = blockIdx.y * BM;
    const int n0   = blockIdx.x * BN;
    const int tcol = tid % (BN/TN);
    const int trow = tid / (BN/TN);

    float acc[TM][TN];
    #pragma unroll
    for (int i=0;i<TM;i++)
        #pragma unroll
        for (int j=0;j<TN;j++) acc[i][j]=0.f;

    for (int k0 = 0; k0 < K; k0 += BK) {
        #pragma unroll
        for (int i = tid*4; i < BM*BK; i += NT*4) {
            int r = i / BK, kc = i % BK;
            int k = k0 + kc;
            float4 v = make_float4(0.f,0.f,0.f,0.f);
            if (k < K) v = *(const float4*)(A + (size_t)(m0+r)*K + k);
            As[kc+0][r]=v.x; As[kc+1][r]=v.y; As[kc+2][r]=v.z; As[kc+3][r]=v.w;
        }
        #pragma unroll
        for (int i = tid*4; i < BN*BK; i += NT*4) {
            int r = i / BK, kc = i % BK;
            int k = k0 + kc;
            float4 v = make_float4(0.f,0.f,0.f,0.f);
            if (k < K) v = *(const float4*)(Bm + (size_t)(n0+r)*K + k);
            Bs[kc+0][r]=v.x; Bs[kc+1][r]=v.y; Bs[kc+2][r]=v.z; Bs[kc+3][r]=v.w;
        }
        __syncthreads();
        #pragma unroll
        for (int kk=0; kk<BK; kk++) {
            float a[TM], bb[TN];
            #pragma unroll
            for (int i=0;i<TM;i++) a[i] = As[kk][trow*TM+i];
            #pragma unroll
            for (int j=0;j<TN;j++) bb[j] = Bs[kk][tcol*TN+j];
            #pragma unroll
            for (int i=0;i<TM;i++)
                #pragma unroll
                for (int j=0;j<TN;j++) acc[i][j] += a[i]*bb[j];
        }
        __syncthreads();
    }

    float s=1.f, mu=0.f, beta=0.f;
    if (EPI==EPI_BN_RELU) { s = bn[0]*rsqrtf(bn[3]+1e-5f); mu = bn[2]; beta = bn[1]; }
    #pragma unroll
    for (int i=0;i<TM;i++) {
        int m = m0 + trow*TM + i;
        #pragma unroll
        for (int j=0;j<TN;j++) {
            int n = n0 + tcol*TN + j;
            float v = acc[i][j];
            if (EPI >= EPI_BIAS)   v += bias[n];
            if (EPI == EPI_BN_RELU){ v = (v-mu)*s + beta; v = fmaxf(v, 0.f); }
            C[(size_t)m*N + n] = v;
        }
    }
}

// ---------------- elementwise / small kernels -------------------------------
__global__ void init_kernel()
{
    int idx = blockIdx.x*blockDim.x + threadIdx.x;
    if (idx < BB*HH) g_h[idx] = 0.f;
    if (idx < BB)    g_inp[idx] = TT;     // SOS token = tagset_size
}

// encoder embedding lookup + max_norm=10 renorm
__global__ void embed_renorm_kernel(const int* __restrict__ tokens,
                                    const float* __restrict__ w2v)
{
    int row = blockIdx.x;                 // 0..BL-1
    int tok = tokens[row];
    const float* src = w2v + (size_t)tok*EE;
    __shared__ float red[128];
    float ss = 0.f;
    for (int k = threadIdx.x; k < EE; k += blockDim.x) { float v = src[k]; ss += v*v; }
    red[threadIdx.x] = ss; __syncthreads();
    for (int s = blockDim.x>>1; s>0; s>>=1) {
        if (threadIdx.x < s) red[threadIdx.x] += red[threadIdx.x+s];
        __syncthreads();
    }
    float sc = fminf(1.f, 10.f/(sqrtf(red[0])+1e-7f));
    for (int k = threadIdx.x; k < EE; k += blockDim.x)
        g_x[(size_t)row*EE + k] = src[k]*sc;
}

// GRU cell update: h = (1-z)*n + z*h ; optionally also write to enc_out slot
__global__ void gru_kernel(const float* __restrict__ gi, int gi_stride,
                           const float* __restrict__ gh,
                           const float* __restrict__ bhh,
                           float* __restrict__ h,
                           float* __restrict__ outp, int out_stride)
{
    int idx = blockIdx.x*blockDim.x + threadIdx.x;
    if (idx >= BB*HH) return;
    int b = idx / HH, j = idx - b*HH;
    const float* gir = gi + (size_t)b*gi_stride;
    const float* ghr = gh + (size_t)b*3*HH;
    float i_r = gir[j], i_z = gir[HH+j], i_n = gir[2*HH+j];
    float h_r = ghr[j]      + bhh[j];
    float h_z = ghr[HH+j]   + bhh[HH+j];
    float h_n = ghr[2*HH+j] + bhh[2*HH+j];
    float r = sigmoidf_(i_r + h_r);
    float z = sigmoidf_(i_z + h_z);
    float n = tanhf(i_n + r*h_n);
    float hv = h[idx];
    float hn = (1.f - z)*n + z*hv;
    h[idx] = hn;
    if (outp) outp[(size_t)b*out_stride + j] = hn;
}

// decoder embedding lookup + max_norm=1 renorm -> g_cat[:, 0:D]
__global__ void dec_embed_kernel(const float* __restrict__ dec_emb)
{
    int b = blockIdx.x, v = threadIdx.x;  // 256 threads = D
    int tok = g_inp[b];
    float val = dec_emb[(size_t)tok*DD + v];
    __shared__ float red[DD];
    red[v] = val*val; __syncthreads();
    for (int s = DD>>1; s>0; s>>=1) { if (v<s) red[v]+=red[v+s]; __syncthreads(); }
    float sc = fminf(1.f, 1.f/(sqrtf(red[0])+1e-7f));
    g_cat[(size_t)b*CATW + v] = val*sc;
}

// attention scores + softmax: aw[b,l] = softmax_l([emb|h] . attn_W[l] + attn_b)
__global__ void attn_kernel(const float* __restrict__ attn_W,
                            const float* __restrict__ attn_b)
{
    int b = blockIdx.x;
    int tid = threadIdx.x, warp = tid>>5, lane = tid&31;
    __shared__ float sc[32];
    const float* emb = g_cat + (size_t)b*CATW;
    const float* hp  = g_h  + (size_t)b*HH;
    for (int l = warp; l < LL; l += 8) {
        const float* w = attn_W + (size_t)l*CATW;
        float acc = 0.f;
        for (int k = lane; k < DD; k += 32) acc += emb[k]*w[k];
        for (int k = lane; k < HH; k += 32) acc += hp[k]*w[DD+k];
        for (int o=16;o;o>>=1) acc += __shfl_xor_sync(0xffffffffu, acc, o);
        if (lane==0) sc[l] = acc + attn_b[l];
    }
    __syncthreads();
    if (warp==0) {
        float v = (lane<LL)? sc[lane] : -1e30f;
        float m = v;
        for (int o=16;o;o>>=1) m = fmaxf(m, __shfl_xor_sync(0xffffffffu, m, o));
        float e = (lane<LL)? expf(v-m) : 0.f;
        float s = e;
        for (int o=16;o;o>>=1) s += __shfl_xor_sync(0xffffffffu, s, o);
        if (lane<LL) g_aw[b*LL+lane] = e/s;
    }
}

// applied[b,j] = sum_l aw[b,l]*enc_out[b,l,j] -> g_cat[:, D:D+H]
__global__ void applied_kernel()
{
    int idx = blockIdx.x*blockDim.x + threadIdx.x;
    if (idx >= BB*HH) return;
    int b = idx/HH, j = idx - b*HH;
    const float* eo = g_enc_out + (size_t)b*LL*HH + j;
    const float* aw = g_aw + b*LL;
    float acc = 0.f;
    #pragma unroll
    for (int l=0;l<LL;l++) acc += aw[l]*eo[(size_t)l*HH];
    g_cat[(size_t)b*CATW + DD + j] = acc;
}

__global__ void bn1_kernel(const float* __restrict__ bn)
{
    int idx = blockIdx.x*blockDim.x + threadIdx.x;
    if (idx >= BB*HH) return;
    float s = bn[0]*rsqrtf(bn[3]+1e-5f);
    g_hb[idx] = (g_h[idx]-bn[2])*s + bn[1];
}

// log_softmax over T + argmax -> output row (b*L + t), next input token
__global__ void lsm_kernel(float* __restrict__ out, int t)
{
    int b = blockIdx.x, v = threadIdx.x;  // T threads
    float x = g_logits[b*TT + v];
    __shared__ float sv[TT]; __shared__ int si[TT]; __shared__ float ssum[TT];
    sv[v]=x; si[v]=v; __syncthreads();
    for (int s=TT>>1; s>0; s>>=1) {
        if (v<s && sv[v+s] > sv[v]) { sv[v]=sv[v+s]; si[v]=si[v+s]; }
        __syncthreads();
    }
    float m = sv[0]; int am = si[0];
    float e = expf(x - m);
    ssum[v]=e; __syncthreads();
    for (int s=TT>>1; s>0; s>>=1) { if (v<s) ssum[v]+=ssum[v+s]; __syncthreads(); }
    float lse = logf(ssum[0]);
    out[((size_t)b*LL + t)*TT + v] = x - m - lse;
    if (v==0) g_inp[b] = am;
}

// ---------------- launch ----------------------------------------------------
extern "C" void kernel_launch(void* const* d_in, const int* in_sizes, int n_in,
                              void* d_out, int out_size)
{
    const int*   tokens  = (const int*)  d_in[0];
    const float* w2v     = (const float*)d_in[1];
    const float* enc_Wih = (const float*)d_in[2];
    const float* enc_Whh = (const float*)d_in[3];
    const float* enc_bih = (const float*)d_in[4];
    const float* enc_bhh = (const float*)d_in[5];
    const float* dec_emb = (const float*)d_in[6];
    const float* attn_W  = (const float*)d_in[7];
    const float* attn_b  = (const float*)d_in[8];
    const float* comb_W  = (const float*)d_in[9];
    const float* comb_b  = (const float*)d_in[10];
    const float* dec_Wih = (const float*)d_in[11];
    const float* dec_Whh = (const float*)d_in[12];
    const float* dec_bih = (const float*)d_in[13];
    const float* dec_bhh = (const float*)d_in[14];
    const float* out_W   = (const float*)d_in[15];
    const float* out_b   = (const float*)d_in[16];
    const float* bn1     = (const float*)d_in[17];
    const float* bn2     = (const float*)d_in[18];
    float* out = (float*)d_out;

    float *px, *pgi_all, *penc_out, *ph, *pgh, *pcat, *po, *pgi_dec, *phb, *plogits;
    cudaGetSymbolAddress((void**)&px,       g_x);
    cudaGetSymbolAddress((void**)&pgi_all,  g_gi_all);
    cudaGetSymbolAddress((void**)&penc_out, g_enc_out);
    cudaGetSymbolAddress((void**)&ph,       g_h);
    cudaGetSymbolAddress((void**)&pgh,      g_gh);
    cudaGetSymbolAddress((void**)&pcat,     g_cat);
    cudaGetSymbolAddress((void**)&po,       g_o);
    cudaGetSymbolAddress((void**)&pgi_dec,  g_gi_dec);
    cudaGetSymbolAddress((void**)&phb,      g_hb);
    cudaGetSymbolAddress((void**)&plogits,  g_logits);

    const int EW = 2048;   // blocks for B*H elementwise at 256 threads

    init_kernel<<<EW, 256>>>();

    // encoder embeddings + input-gate GEMM for all steps
    embed_renorm_kernel<<<BL, 128>>>(tokens, w2v);
    sgemm_nt<64,64,16,4,4,EPI_BIAS><<<dim3(3*HH/64, BL/64), 256>>>(
        px, enc_Wih, pgi_all, BL, 3*HH, EE, enc_bih, nullptr);

    // encoder recurrence
    for (int t = 0; t < LL; t++) {
        sgemm_nt<64,64,16,4,4,EPI_NONE><<<dim3(3*HH/64, BB/64), 256>>>(
            ph, enc_Whh, pgh, BB, 3*HH, HH, nullptr, nullptr);
        gru_kernel<<<EW, 256>>>(pgi_all + (size_t)t*3*HH, LL*3*HH, pgh, enc_bhh,
                                ph, penc_out + (size_t)t*HH, LL*HH);
    }

    // greedy attention decoder
    for (int t = 0; t < LL; t++) {
        dec_embed_kernel<<<BB, DD>>>(dec_emb);
        attn_kernel<<<BB, 256>>>(attn_W, attn_b);
        applied_kernel<<<EW, 256>>>();
        sgemm_nt<64,64,16,4,4,EPI_BN_RELU><<<dim3(HH/64, BB/64), 256>>>(
            pcat, comb_W, po, BB, HH, CATW, comb_b, bn2);
        sgemm_nt<64,64,16,4,4,EPI_BIAS><<<dim3(3*HH/64, BB/64), 256>>>(
            po, dec_Wih, pgi_dec, BB, 3*HH, HH, dec_bih, nullptr);
        sgemm_nt<64,64,16,4,4,EPI_NONE><<<dim3(3*HH/64, BB/64), 256>>>(
            ph, dec_Whh, pgh, BB, 3*HH, HH, nullptr, nullptr);
        gru_kernel<<<EW, 256>>>(pgi_dec, 3*HH, pgh, dec_bhh, ph, nullptr, 0);
        bn1_kernel<<<EW, 256>>>(bn1);
        sgemm_nt<32,32,32,2,2,EPI_BIAS><<<dim3(TT/32, BB/32), 256>>>(
            phb, out_W, plogits, BB, TT, HH, out_b, nullptr);
        lsm_kernel<<<BB, TT>>>(out, t);
    }
}

// round 3
// speedup vs baseline: 1.2739x; 1.2739x over previous
#include <cuda_runtime.h>
#include <math.h>

// Problem constants
#define BB 512
#define LL 25
#define EE 300
#define HH 1024
#define DD 256
#define TT 128
#define BL (BB*LL)          // 12800
#define CATW (DD+HH)        // 1280

typedef unsigned long long ull_t;

// ---------------- scratch (device globals; no allocation allowed) -----------
__device__ float g_x[BL*EE];                    // renormed encoder embeddings
__device__ float g_gi_all[BL*3*HH];             // (B*L, 3H) input gates, all steps
__device__ float g_enc_out[BL*HH];              // (B*L, H) encoder outputs
__device__ float g_h[BB*HH];                    // recurrent hidden (enc then dec)
__device__ float g_gh[BB*3*HH];                 // h @ Whh^T
__device__ float g_cat[BB*CATW];                // [emb | applied]
__device__ float g_o[BB*HH];                    // combined+bn+relu
__device__ float g_gi_dec[BB*3*HH];             // decoder input gates
__device__ int   g_inp[BB];

__device__ __forceinline__ float sigmoidf_(float x) { return 1.f/(1.f+expf(-x)); }

// packed f32x2 FMA: d = a*b + d  (Blackwell; ptxas never emits FFMA2 from C++)
__device__ __forceinline__ void ffma2(float2& d, const float2& a, const float2& b) {
    asm("fma.rn.f32x2 %0, %1, %2, %0;"
        : "+l"(*reinterpret_cast<ull_t*>(&d))
        : "l"(*reinterpret_cast<const ull_t*>(&a)),
          "l"(*reinterpret_cast<const ull_t*>(&b)));
}

__device__ __forceinline__ float4 ldg4_guard(const float* p, int rem) {
    if (rem >= 4) return *(const float4*)p;
    float4 v = make_float4(0.f,0.f,0.f,0.f);
    if (rem > 0) v.x = p[0];
    if (rem > 1) v.y = p[1];
    if (rem > 2) v.z = p[2];
    return v;
}

// ---------------- SGEMM (NT): C(M,N) = A(M,K) * B(N,K)^T --------------------
// 64x64x16 tile, 128 threads, 8(Mpairs)x4 microtile, f32x2 FMA, double buffer.
// Requires M%64==0, N%64==0. K arbitrary (zero-filled tail).
enum { EPI_NONE=0, EPI_BIAS=1, EPI_BN_RELU=2 };

template<int EPI>
__global__ __launch_bounds__(128) void sgemm_f2(
    const float* __restrict__ A, const float* __restrict__ Bm, float* __restrict__ C,
    int M, int N, int K,
    const float* __restrict__ bias, const float* __restrict__ bn)
{
    constexpr int BM=64, BN=64, BK=16, PAD=4;
    __shared__ float As[2][BK][BM+PAD];
    __shared__ float Bs[2][BK][BN+PAD];

    const int tid  = threadIdx.x;
    const int m0   = blockIdx.y * BM;
    const int n0   = blockIdx.x * BN;
    const int tcol = tid & 15;     // 16 cols of 4
    const int trow = tid >> 4;     // 8 rows of 8
    const int lr   = tid >> 2;     // 0..31 staging row
    const int lc   = (tid & 3) << 2; // 0,4,8,12 staging k-offset

    float2 acc[4][4];
    #pragma unroll
    for (int i=0;i<4;i++)
        #pragma unroll
        for (int j=0;j<4;j++) acc[i][j] = make_float2(0.f,0.f);

    float4 ra[2], rb[2];

    auto ldg_tiles = [&](int k0) {
        int rem = K - (k0 + lc);
        #pragma unroll
        for (int s=0;s<2;s++) {
            const float* pa = A  + (size_t)(m0+lr+s*32)*K + k0 + lc;
            const float* pb = Bm + (size_t)(n0+lr+s*32)*K + k0 + lc;
            ra[s] = ldg4_guard(pa, rem);
            rb[s] = ldg4_guard(pb, rem);
        }
    };
    auto sts_tiles = [&](int buf) {
        #pragma unroll
        for (int s=0;s<2;s++) {
            int r = lr + s*32;
            As[buf][lc+0][r]=ra[s].x; As[buf][lc+1][r]=ra[s].y;
            As[buf][lc+2][r]=ra[s].z; As[buf][lc+3][r]=ra[s].w;
            Bs[buf][lc+0][r]=rb[s].x; Bs[buf][lc+1][r]=rb[s].y;
            Bs[buf][lc+2][r]=rb[s].z; Bs[buf][lc+3][r]=rb[s].w;
        }
    };

    ldg_tiles(0);
    sts_tiles(0);
    __syncthreads();

    int buf = 0;
    const int nk = (K + BK - 1) / BK;
    for (int it = 0; it < nk; it++) {
        if (it + 1 < nk) ldg_tiles((it+1)*BK);
        float (*as)[BM+PAD] = As[buf];
        float (*bs)[BN+PAD] = Bs[buf];
        #pragma unroll
        for (int kk=0; kk<BK; kk++) {
            float4 a0 = *(const float4*)&as[kk][trow*8];
            float4 a1 = *(const float4*)&as[kk][trow*8+4];
            float4 bv = *(const float4*)&bs[kk][tcol*4];
            float2 ap[4];
            ap[0] = make_float2(a0.x,a0.y); ap[1] = make_float2(a0.z,a0.w);
            ap[2] = make_float2(a1.x,a1.y); ap[3] = make_float2(a1.z,a1.w);
            float bj[4] = {bv.x, bv.y, bv.z, bv.w};
            #pragma unroll
            for (int j=0;j<4;j++) {
                float2 bb = make_float2(bj[j], bj[j]);
                #pragma unroll
                for (int i=0;i<4;i++) ffma2(acc[i][j], ap[i], bb);
            }
        }
        if (it + 1 < nk) {
            sts_tiles(buf ^ 1);
            __syncthreads();
            buf ^= 1;
        }
    }

    float s=1.f, mu=0.f, beta=0.f;
    if (EPI==EPI_BN_RELU) { s = bn[0]*rsqrtf(bn[3]+1e-5f); mu = bn[2]; beta = bn[1]; }
    float bsv[4];
    if (EPI >= EPI_BIAS) {
        #pragma unroll
        for (int j=0;j<4;j++) bsv[j] = bias[n0 + tcol*4 + j];
    }
    #pragma unroll
    for (int i=0;i<4;i++) {
        #pragma unroll
        for (int pm=0;pm<2;pm++) {
            int m = m0 + trow*8 + i*2 + pm;
            float4 v;
            v.x = pm ? acc[i][0].y : acc[i][0].x;
            v.y = pm ? acc[i][1].y : acc[i][1].x;
            v.z = pm ? acc[i][2].y : acc[i][2].x;
            v.w = pm ? acc[i][3].y : acc[i][3].x;
            if (EPI >= EPI_BIAS) { v.x+=bsv[0]; v.y+=bsv[1]; v.z+=bsv[2]; v.w+=bsv[3]; }
            if (EPI == EPI_BN_RELU) {
                v.x = fmaxf((v.x-mu)*s+beta, 0.f);
                v.y = fmaxf((v.y-mu)*s+beta, 0.f);
                v.z = fmaxf((v.z-mu)*s+beta, 0.f);
                v.w = fmaxf((v.w-mu)*s+beta, 0.f);
            }
            *(float4*)(C + (size_t)m*N + n0 + tcol*4) = v;
        }
    }
}

// ---------------- small / fused kernels -------------------------------------
__global__ void init_kernel()
{
    int idx = blockIdx.x*blockDim.x + threadIdx.x;
    if (idx < BB*HH) g_h[idx] = 0.f;
    if (idx < BB)    g_inp[idx] = TT;     // SOS token = tagset_size
}

// encoder embedding lookup + max_norm=10 renorm
__global__ void embed_renorm_kernel(const int* __restrict__ tokens,
                                    const float* __restrict__ w2v)
{
    int row = blockIdx.x;                 // 0..BL-1
    int tok = tokens[row];
    const float* src = w2v + (size_t)tok*EE;
    __shared__ float red[128];
    float ss = 0.f;
    for (int k = threadIdx.x; k < EE; k += blockDim.x) { float v = src[k]; ss += v*v; }
    red[threadIdx.x] = ss; __syncthreads();
    for (int s = blockDim.x>>1; s>0; s>>=1) {
        if (threadIdx.x < s) red[threadIdx.x] += red[threadIdx.x+s];
        __syncthreads();
    }
    float sc = fminf(1.f, 10.f/(sqrtf(red[0])+1e-7f));
    for (int k = threadIdx.x; k < EE; k += blockDim.x)
        g_x[(size_t)row*EE + k] = src[k]*sc;
}

// GRU cell update: h = (1-z)*n + z*h ; optionally also write to enc_out slot
__global__ void gru_kernel(const float* __restrict__ gi, int gi_stride,
                           const float* __restrict__ gh,
                           const float* __restrict__ bhh,
                           float* __restrict__ h,
                           float* __restrict__ outp, int out_stride)
{
    int idx = blockIdx.x*blockDim.x + threadIdx.x;
    if (idx >= BB*HH) return;
    int b = idx / HH, j = idx - b*HH;
    const float* gir = gi + (size_t)b*gi_stride;
    const float* ghr = gh + (size_t)b*3*HH;
    float i_r = gir[j], i_z = gir[HH+j], i_n = gir[2*HH+j];
    float h_r = ghr[j]      + bhh[j];
    float h_z = ghr[HH+j]   + bhh[HH+j];
    float h_n = ghr[2*HH+j] + bhh[2*HH+j];
    float r = sigmoidf_(i_r + h_r);
    float z = sigmoidf_(i_z + h_z);
    float n = tanhf(i_n + r*h_n);
    float hv = h[idx];
    float hn = (1.f - z)*n + z*hv;
    h[idx] = hn;
    if (outp) outp[(size_t)b*out_stride + j] = hn;
}

// fused: decoder embedding (+renorm) -> attention scores -> softmax -> applied
// one block per batch element, 256 threads
__global__ __launch_bounds__(256) void dec_attn_kernel(
    const float* __restrict__ dec_emb,
    const float* __restrict__ attn_W, const float* __restrict__ attn_b)
{
    int b = blockIdx.x, tid = threadIdx.x;
    __shared__ float semb[DD];
    __shared__ float sh[HH];
    __shared__ float saw[32];
    __shared__ float red[256];

    int tok = g_inp[b];
    float val = dec_emb[(size_t)tok*DD + tid];   // tid < 256 == DD
    red[tid] = val*val; __syncthreads();
    for (int s=128; s>0; s>>=1) { if (tid<s) red[tid]+=red[tid+s]; __syncthreads(); }
    float sc = fminf(1.f, 1.f/(sqrtf(red[0])+1e-7f));
    float e = val*sc;
    semb[tid] = e;
    g_cat[(size_t)b*CATW + tid] = e;
    for (int k = tid; k < HH; k += 256) sh[k] = g_h[(size_t)b*HH + k];
    __syncthreads();

    int warp = tid>>5, lane = tid&31;
    for (int l = warp; l < LL; l += 8) {
        const float* w = attn_W + (size_t)l*CATW;
        float acc = 0.f;
        for (int k = lane; k < DD; k += 32) acc += semb[k]*w[k];
        for (int k = lane; k < HH; k += 32) acc += sh[k]*w[DD+k];
        for (int o=16;o;o>>=1) acc += __shfl_xor_sync(0xffffffffu, acc, o);
        if (lane==0) saw[l] = acc + attn_b[l];
    }
    __syncthreads();
    if (warp==0) {
        float v = (lane<LL)? saw[lane] : -1e30f;
        float m = v;
        for (int o=16;o;o>>=1) m = fmaxf(m, __shfl_xor_sync(0xffffffffu, m, o));
        float ex = (lane<LL)? expf(v-m) : 0.f;
        float sm = ex;
        for (int o=16;o;o>>=1) sm += __shfl_xor_sync(0xffffffffu, sm, o);
        if (lane<LL) saw[lane] = ex/sm;
    }
    __syncthreads();

    const float* eo = g_enc_out + (size_t)b*LL*HH;
    for (int j = tid; j < HH; j += 256) {
        float acc = 0.f;
        #pragma unroll
        for (int l=0;l<LL;l++) acc += saw[l]*eo[(size_t)l*HH + j];
        g_cat[(size_t)b*CATW + DD + j] = acc;
    }
}

// fused: bn1(h) @ out_W^T + out_b -> log_softmax -> argmax -> next input
// one block per batch element, 256 threads
__global__ __launch_bounds__(256) void out_lsm_kernel(
    const float* __restrict__ Wt, const float* __restrict__ ob,
    const float* __restrict__ bn, float* __restrict__ out, int t)
{
    constexpr int CH = 64;
    __shared__ float hsh[HH];
    __shared__ float Ws[TT][CH+1];
    __shared__ float red[256];
    __shared__ int   redi[128];

    int b = blockIdx.x, tid = threadIdx.x;
    int v = tid & 127, half = tid >> 7;
    float s = bn[0]*rsqrtf(bn[3]+1e-5f), mu = bn[2], beta = bn[1];
    for (int k = tid; k < HH; k += 256)
        hsh[k] = (g_h[(size_t)b*HH + k] - mu)*s + beta;

    float acc = 0.f;
    for (int k0 = 0; k0 < HH; k0 += CH) {
        __syncthreads();
        for (int i = tid; i < TT*CH; i += 256) {
            int r = i >> 6, c = i & 63;
            Ws[r][c] = Wt[(size_t)r*HH + k0 + c];
        }
        __syncthreads();
        const int kb = half*32;
        #pragma unroll
        for (int k = 0; k < 32; k++)
            acc += hsh[k0 + kb + k] * Ws[v][kb + k];
    }
    __syncthreads();
    red[tid] = acc; __syncthreads();
    float x = 0.f;
    if (tid < 128) x = red[tid] + red[tid+128] + ob[tid];
    __syncthreads();
    if (tid < 128) { red[tid] = x; redi[tid] = tid; }
    __syncthreads();
    for (int st = 64; st > 0; st >>= 1) {
        if (tid < st) {
            if (red[tid+st] > red[tid]) { red[tid]=red[tid+st]; redi[tid]=redi[tid+st]; }
        }
        __syncthreads();
    }
    float m = red[0]; int am = redi[0];
    __syncthreads();
    red[tid] = (tid < 128) ? expf(x - m) : 0.f;
    __syncthreads();
    for (int st = 128; st > 0; st >>= 1) { if (tid<st) red[tid]+=red[tid+st]; __syncthreads(); }
    float lse = logf(red[0]);
    if (tid < 128) out[((size_t)b*LL + t)*TT + tid] = x - m - lse;
    if (tid == 0) g_inp[b] = am;
}

// ---------------- launch ----------------------------------------------------
extern "C" void kernel_launch(void* const* d_in, const int* in_sizes, int n_in,
                              void* d_out, int out_size)
{
    const int*   tokens  = (const int*)  d_in[0];
    const float* w2v     = (const float*)d_in[1];
    const float* enc_Wih = (const float*)d_in[2];
    const float* enc_Whh = (const float*)d_in[3];
    const float* enc_bih = (const float*)d_in[4];
    const float* enc_bhh = (const float*)d_in[5];
    const float* dec_emb = (const float*)d_in[6];
    const float* attn_W  = (const float*)d_in[7];
    const float* attn_b  = (const float*)d_in[8];
    const float* comb_W  = (const float*)d_in[9];
    const float* comb_b  = (const float*)d_in[10];
    const float* dec_Wih = (const float*)d_in[11];
    const float* dec_Whh = (const float*)d_in[12];
    const float* dec_bih = (const float*)d_in[13];
    const float* dec_bhh = (const float*)d_in[14];
    const float* out_W   = (const float*)d_in[15];
    const float* out_b   = (const float*)d_in[16];
    const float* bn1     = (const float*)d_in[17];
    const float* bn2     = (const float*)d_in[18];
    float* out = (float*)d_out;

    float *px, *pgi_all, *penc_out, *ph, *pgh, *pcat, *po, *pgi_dec;
    cudaGetSymbolAddress((void**)&px,       g_x);
    cudaGetSymbolAddress((void**)&pgi_all,  g_gi_all);
    cudaGetSymbolAddress((void**)&penc_out, g_enc_out);
    cudaGetSymbolAddress((void**)&ph,       g_h);
    cudaGetSymbolAddress((void**)&pgh,      g_gh);
    cudaGetSymbolAddress((void**)&pcat,     g_cat);
    cudaGetSymbolAddress((void**)&po,       g_o);
    cudaGetSymbolAddress((void**)&pgi_dec,  g_gi_dec);

    const int EW = 2048;   // blocks for B*H elementwise at 256 threads

    init_kernel<<<EW, 256>>>();

    // encoder embeddings + input-gate GEMM for all steps
    embed_renorm_kernel<<<BL, 128>>>(tokens, w2v);
    sgemm_f2<EPI_BIAS><<<dim3(3*HH/64, BL/64), 128>>>(
        px, enc_Wih, pgi_all, BL, 3*HH, EE, enc_bih, nullptr);

    // encoder recurrence
    for (int t = 0; t < LL; t++) {
        sgemm_f2<EPI_NONE><<<dim3(3*HH/64, BB/64), 128>>>(
            ph, enc_Whh, pgh, BB, 3*HH, HH, nullptr, nullptr);
        gru_kernel<<<EW, 256>>>(pgi_all + (size_t)t*3*HH, LL*3*HH, pgh, enc_bhh,
                                ph, penc_out + (size_t)t*HH, LL*HH);
    }

    // greedy attention decoder
    for (int t = 0; t < LL; t++) {
        dec_attn_kernel<<<BB, 256>>>(dec_emb, attn_W, attn_b);
        sgemm_f2<EPI_BN_RELU><<<dim3(HH/64, BB/64), 128>>>(
            pcat, comb_W, po, BB, HH, CATW, comb_b, bn2);
        sgemm_f2<EPI_BIAS><<<dim3(3*HH/64, BB/64), 128>>>(
            po, dec_Wih, pgi_dec, BB, 3*HH, HH, dec_bih, nullptr);
        sgemm_f2<EPI_NONE><<<dim3(3*HH/64, BB/64), 128>>>(
            ph, dec_Whh, pgh, BB, 3*HH, HH, nullptr, nullptr);
        gru_kernel<<<EW, 256>>>(pgi_dec, 3*HH, pgh, dec_bhh, ph, nullptr, 0);
        out_lsm_kernel<<<BB, 256>>>(out_W, out_b, bn1, out, t);
    }
}